// round 15
// baseline (speedup 1.0000x reference)
#include <cuda_runtime.h>
#include <cstdint>

// Pooling_38706245271888 — GB300 sm_103a
//   word_vectors        [B, T, D]  float32
//   sent_rep_token_ids  [B, S]     int32
//   sent_rep_mask       [B, S]     int32
//   sent_lengths        [B, S]     int32
//   sent_lengths_mask   [B, S]     int32
// Output: concat([rep_vec, mean_vec], axis=1) -> [B, 2S, D] float32 (+ mask tail).
#define PB 16
#define PT 4096
#define PD 768
#define PS 64
#define NTHR 192          // 192*4 == 768: thread i owns float4 at dim 4*i
#define UNR 16            // L=64 divisible by 16 -> 4 iters/sentence, no epilogue

// R13 structure (35.3us / DRAM 75.7%) with unroll deepened 8 -> 16. ptxas
// software-pipelines the load batch (R13: regs stayed 40 at unroll-8), so the
// bigger window raises effective MLP without blowing the register budget.
// Hot loop stays pure load+accumulate (R10/R12: any extra in-loop work costs
// DRAM%). Rep gather is hoisted before the reduce barrier to overlap latency.
__global__ __launch_bounds__(NTHR, 7) void pool_kernel(
    const float* __restrict__ wv,
    const int* __restrict__ rep_ids,
    const int* __restrict__ rep_mask,
    const int* __restrict__ lengths,
    const int* __restrict__ len_mask,
    float* __restrict__ out,
    int write_mask_tail)
{
    const int blk = blockIdx.x;          // 0 .. B*S-1
    const int b = blk / PS;
    const int j = blk % PS;
    const int tid = threadIdx.x;         // 0 .. 191
    const int d4 = tid * 4;

    // --- sentence span via warp-parallel masked reduce over lengths ---
    __shared__ int s_len[PS];
    __shared__ int s_span[2];
    if (tid < PS) s_len[tid] = lengths[b * PS + tid];
    __syncthreads();
    if (tid < 32) {
        int c = ((tid      < j) ? s_len[tid]      : 0)
              + ((tid + 32 < j) ? s_len[tid + 32] : 0);
        #pragma unroll
        for (int o = 16; o > 0; o >>= 1) c += __shfl_down_sync(0xffffffffu, c, o);
        if (tid == 0) {
            int start = c;
            int end = start + s_len[j];
            if (start > PT) start = PT;  // overflow bucket dropped
            if (end   > PT) end   = PT;
            if (end < start) end = start;
            s_span[0] = start;
            s_span[1] = end;
        }
    }
    __syncthreads();
    const int start = s_span[0];
    const int end   = s_span[1];

    const float* __restrict__ base = wv + (size_t)b * PT * PD;

    // --- segment sum + per-component nonzero count, unroll-16, loads first ---
    float4 sum = make_float4(0.f, 0.f, 0.f, 0.f);
    float4 cnt = make_float4(0.f, 0.f, 0.f, 0.f);

    const float* p = base + (size_t)start * PD + d4;
    int t = start;
    for (; t + UNR <= end; t += UNR, p += UNR * PD) {
        float4 v[UNR];
        #pragma unroll
        for (int k = 0; k < UNR; k++)
            v[k] = __ldcs((const float4*)(p + (size_t)k * PD));
        #pragma unroll
        for (int k = 0; k < UNR; k++) {
            sum.x += v[k].x; sum.y += v[k].y; sum.z += v[k].z; sum.w += v[k].w;
            cnt.x += (v[k].x != 0.f) ? 1.f : 0.f;
            cnt.y += (v[k].y != 0.f) ? 1.f : 0.f;
            cnt.z += (v[k].z != 0.f) ? 1.f : 0.f;
            cnt.w += (v[k].w != 0.f) ? 1.f : 0.f;
        }
    }
    for (; t + 4 <= end; t += 4, p += 4 * PD) {       // epilogue (unused on L=64)
        float4 v[4];
        #pragma unroll
        for (int k = 0; k < 4; k++)
            v[k] = __ldcs((const float4*)(p + (size_t)k * PD));
        #pragma unroll
        for (int k = 0; k < 4; k++) {
            sum.x += v[k].x; sum.y += v[k].y; sum.z += v[k].z; sum.w += v[k].w;
            cnt.x += (v[k].x != 0.f) ? 1.f : 0.f;
            cnt.y += (v[k].y != 0.f) ? 1.f : 0.f;
            cnt.z += (v[k].z != 0.f) ? 1.f : 0.f;
            cnt.w += (v[k].w != 0.f) ? 1.f : 0.f;
        }
    }
    for (; t < end; t++, p += PD) {
        float4 v = __ldcs((const float4*)(p));
        sum.x += v.x; sum.y += v.y; sum.z += v.z; sum.w += v.w;
        cnt.x += (v.x != 0.f) ? 1.f : 0.f;
        cnt.y += (v.y != 0.f) ? 1.f : 0.f;
        cnt.z += (v.z != 0.f) ? 1.f : 0.f;
        cnt.w += (v.w != 0.f) ? 1.f : 0.f;
    }

    // --- rep gather issued BEFORE the reduce barrier: overlaps its latency ---
    int id = rep_ids[b * PS + j];
    if (id < 0) id = 0;
    if (id >= PT) id = PT - 1;
    float4 rv = *(const float4*)(base + (size_t)id * PD + d4);

    // --- block reduce total count (empty-segment fallback detection) ---
    __shared__ float red[256];
    red[tid] = cnt.x + cnt.y + cnt.z + cnt.w;
    if (tid < 64) red[192 + tid] = 0.f;
    __syncthreads();
    for (int off = 128; off > 0; off >>= 1) {
        if (tid < off) red[tid] += red[tid + off];
        __syncthreads();
    }
    const bool empty = (red[0] == 0.f);

    const float lm = len_mask[b * PS + j] ? 1.f : 0.f;
    const float rm = rep_mask[b * PS + j] ? 1.f : 0.f;

    // --- mean vector (divide by per-dim nonzero count, min 1) ---
    float4 mv;
    if (empty) {
        mv = *(const float4*)(wv + d4);   // fallback: word_vectors[0, 0, :]
    } else {
        mv.x = sum.x / ((cnt.x == 0.f) ? 1.f : cnt.x);
        mv.y = sum.y / ((cnt.y == 0.f) ? 1.f : cnt.y);
        mv.z = sum.z / ((cnt.z == 0.f) ? 1.f : cnt.z);
        mv.w = sum.w / ((cnt.w == 0.f) ? 1.f : cnt.w);
    }
    mv.x *= lm; mv.y *= lm; mv.z *= lm; mv.w *= lm;
    rv.x *= rm; rv.y *= rm; rv.z *= rm; rv.w *= rm;

    // --- write: out[b, 0:S, :] = rep, out[b, S:2S, :] = mean ---
    float* orow_rep  = out + ((size_t)b * 2 * PS + j) * PD + d4;
    float* orow_mean = out + ((size_t)b * 2 * PS + PS + j) * PD + d4;
    *(float4*)orow_rep  = rv;
    *(float4*)orow_mean = mv;

    // --- mask tail (output_mask), if the harness buffer includes it ---
    if (write_mask_tail && tid == 0) {
        float* mt = out + (size_t)PB * 2 * PS * PD;
        mt[b * 2 * PS + j]      = rm;
        mt[b * 2 * PS + PS + j] = lm;
    }
}

extern "C" void kernel_launch(void* const* d_in, const int* in_sizes, int n_in,
                              void* d_out, int out_size) {
    const float* wv       = (const float*)d_in[0];
    const int*   rep_ids  = (const int*)d_in[1];
    const int*   rep_mask = (const int*)d_in[2];
    const int*   lengths  = (const int*)d_in[3];
    const int*   len_mask = (const int*)d_in[4];
    float* out = (float*)d_out;

    const int vec_elems  = PB * 2 * PS * PD;   // 1,572,864
    const int mask_elems = PB * 2 * PS;        // 2,048
    int write_mask_tail = (out_size >= vec_elems + mask_elems) ? 1 : 0;

    pool_kernel<<<PB * PS, NTHR>>>(wv, rep_ids, rep_mask, lengths, len_mask,
                                   out, write_mask_tail);
}